// round 13
// baseline (speedup 1.0000x reference)
#include <cuda_runtime.h>
#include <cuda_fp16.h>
#include <cstdint>

// Problem constants (match reference)
#define Lc 4
#define Gc 20000
#define Cc 128
#define Ec 320000
#define KDc 16
#define NROWS (Lc*Gc)          // 80000 state rows of length 128
#define LN_EPS 1e-5f
#define CAP 192                // padded edge-bucket capacity per row

typedef unsigned long long u64;

#define PREP_BLOCKS (NROWS/32)   // 2500
#define SPMM_BLOCKS (Gc/2)       // 10000
#define KQ_BLOCKS   (Gc/8)       // 2500

// ---------------- device scratch (static: no allocation APIs) --------------
__device__ __half g_xh[(size_t)Lc*Gc*Cc];    // fp16 copy of x
__device__ __half g_Ah[(size_t)Lc*Gc*Cc];    // fp16 A = spmm(x)
__device__ __half g_Bh[(size_t)Lc*Gc*Cc];    // fp16 B = spmm(A)
__device__ float g_kqx[(size_t)Gc*128];      // [g][l*32+d] fp32 projections of x
__device__ float g_kqA[(size_t)Gc*128];      // spmm(kqx)
__device__ float g_kqB[(size_t)Gc*128];      // spmm(kqA)
__device__ int   g_cnt[Gc];                  // row degree (built by scatter)
__device__ int2  g_edgeP[(size_t)Gc*CAP];    // (col, f32bits(val*0.5)) padded
// paired layout: g_Wkq2[(j2*32+d)*2 + {0,1}] = W(2*j2, d), W(2*j2+1, d)
__device__ float g_Wkq2[(Cc/2)*32*2];
// j-paired Wv: g_Wv2[(j2*Cc + c)*2 + {0,1}] = Wv[2*j2][c], Wv[2*j2+1][c]
__device__ float g_Wv2[Cc*Cc];

// ---------------- helpers ---------------------------------------------------
__device__ __forceinline__ void fma2(u64& acc, u64 a, u64 b) {
    asm("fma.rn.f32x2 %0, %1, %2, %3;" : "=l"(acc) : "l"(a), "l"(b), "l"(acc));
}
__device__ __forceinline__ void unpack2(u64 v, float& lo, float& hi) {
    asm("mov.b64 {%0,%1}, %2;" : "=f"(lo), "=f"(hi) : "l"(v));
}
__device__ __forceinline__ float psum(u64 v) {
    float lo, hi;
    unpack2(v, lo, hi);
    return lo + hi;
}
__device__ __forceinline__ float2 h2f2(unsigned u) {
    __half2 h = *reinterpret_cast<__half2*>(&u);
    return __half22float2(h);
}
__device__ __forceinline__ unsigned f2h2(float a, float b) {
    __half2 h = __floats2half2_rn(a, b);
    return *reinterpret_cast<unsigned*>(&h);
}

// ---------------- setup: zero counters + paired Wkq2 + paired Wv2 ----------
__global__ void setup_kernel(const float* __restrict__ Wk,
                             const float* __restrict__ Wq,
                             const float* __restrict__ Wv) {
    int i = blockIdx.x * blockDim.x + threadIdx.x;
    if (i < Gc) g_cnt[i] = 0;
    if (i < (Cc / 2) * 32) {
        int j2 = i >> 5, d = i & 31;
        const float* W = (d < 16) ? Wk : Wq;
        int dd = d & 15;
        g_Wkq2[i * 2 + 0] = W[(2 * j2 + 0) * KDc + dd];
        g_Wkq2[i * 2 + 1] = W[(2 * j2 + 1) * KDc + dd];
    }
    if (i < Cc * Cc) {
        int j = i >> 7, c = i & 127;
        g_Wv2[((j >> 1) * Cc + c) * 2 + (j & 1)] = Wv[i];
    }
}

// ---------------- prep tile: kqx projections + fp16 convert of x ------------
// Block = 32 flat rows (same l; Gc%32==0). 8 warps x 4 rows; lane = kq dim.
__device__ __forceinline__ void prep_tile(const float* __restrict__ x, int b) {
    __shared__ __align__(16) float s[32][Cc];
    __shared__ __align__(16) float wkq2[(Cc/2)*32*2];
    int tid = threadIdx.x;                    // 256

    const float4* gp = reinterpret_cast<const float4*>(x + (size_t)b * 32 * Cc);
    float4* sp = reinterpret_cast<float4*>(&s[0][0]);
    const float4* wg = reinterpret_cast<const float4*>(g_Wkq2);
    float4* wsp = reinterpret_cast<float4*>(wkq2);
    #pragma unroll
    for (int i = 0; i < 4; i++) {
        sp[tid + i * 256]  = gp[tid + i * 256];
        wsp[tid + i * 256] = wg[tid + i * 256];
    }
    __syncthreads();

    // fp16 conversion of the tile (coalesced half2 writes)
    {
        const float* sf = &s[0][0];
        unsigned* dsth = reinterpret_cast<unsigned*>(g_xh + (size_t)b * 32 * Cc);
        #pragma unroll
        for (int i = 0; i < 8; i++) {
            int h = tid + i * 256;            // 2048 half2
            dsth[h] = f2h2(sf[h * 2], sf[h * 2 + 1]);
        }
    }

    int w = tid >> 5, lane = tid & 31;
    u64 acc[4] = {0ull, 0ull, 0ull, 0ull};
    #pragma unroll 8
    for (int j2 = 0; j2 < Cc / 2; j2++) {
        u64 w2 = *reinterpret_cast<const u64*>(wkq2 + (j2 * 32 + lane) * 2);
        #pragma unroll
        for (int r = 0; r < 4; r++) {
            u64 sv = *reinterpret_cast<const u64*>(&s[w * 4 + r][j2 * 2]);
            fma2(acc[r], sv, w2);
        }
    }
    int Rt = b * 32 + w * 4;
    int l = Rt / Gc, g = Rt - l * Gc;         // whole tile same l
    #pragma unroll
    for (int r = 0; r < 4; r++)
        g_kqx[(size_t)(g + r) * 128 + l * 32 + lane] = psum(acc[r]);
}

// ---------------- scatter (padded buckets) + prep ---------------------------
__global__ void scatter_prep_kernel(const int* __restrict__ erow,
                                    const int* __restrict__ ecol,
                                    const float* __restrict__ ev,
                                    int E, int eblk,
                                    const float* __restrict__ x) {
    if ((int)blockIdx.x < eblk) {
        int i = (blockIdx.x * blockDim.x + threadIdx.x) * 4;
        if (i + 3 < E) {
            int4   r = *reinterpret_cast<const int4*>(erow + i);
            int4   c = *reinterpret_cast<const int4*>(ecol + i);
            float4 v = *reinterpret_cast<const float4*>(ev + i);
            int p;
            p = atomicAdd(&g_cnt[r.x], 1);
            g_edgeP[(size_t)r.x * CAP + p] = make_int2(c.x, __float_as_int(v.x * 0.5f));
            p = atomicAdd(&g_cnt[r.y], 1);
            g_edgeP[(size_t)r.y * CAP + p] = make_int2(c.y, __float_as_int(v.y * 0.5f));
            p = atomicAdd(&g_cnt[r.z], 1);
            g_edgeP[(size_t)r.z * CAP + p] = make_int2(c.z, __float_as_int(v.z * 0.5f));
            p = atomicAdd(&g_cnt[r.w], 1);
            g_edgeP[(size_t)r.w * CAP + p] = make_int2(c.w, __float_as_int(v.w * 0.5f));
        } else {
            for (int k = i; k < E; k++) {
                int p = atomicAdd(&g_cnt[erow[k]], 1);
                g_edgeP[(size_t)erow[k] * CAP + p] =
                    make_int2(ecol[k], __float_as_int(ev[k] * 0.5f));
            }
        }
    } else {
        prep_tile(x, blockIdx.x - eblk);
    }
}

// ---------------- fp16 spmm block: 2 g x 4 l warps, LDG.64 gathers ----------
__device__ __forceinline__ void spmm16_block(const __half* __restrict__ src,
                                             __half* __restrict__ dst,
                                             int g0) {
    __shared__ __align__(16) int2 se[2][CAP];
    __shared__ int ncnt[2];
    int tid = threadIdx.x;

    if (tid < 2) ncnt[tid] = g_cnt[g0 + tid];
    __syncthreads();
    int n0 = ncnt[0], n1 = ncnt[1];
    if (tid < n0) se[0][tid] = g_edgeP[(size_t)g0 * CAP + tid];
    if (tid < n1) se[1][tid] = g_edgeP[(size_t)(g0 + 1) * CAP + tid];
    __syncthreads();

    int w = tid >> 5, lane = tid & 31;
    int gi = w >> 2;
    int g  = g0 + gi;
    int l  = w & 3;
    int n  = gi ? n1 : n0;
    const int2* ep = se[gi];
    const __half* srcb = src + (size_t)l * Gc * Cc + lane * 4;

    float4 acc = make_float4(0.f, 0.f, 0.f, 0.f);
    int k = 0;
    for (; k + 4 <= n; k += 4) {
        int4 e01 = *reinterpret_cast<const int4*>(ep + k);       // LDS broadcast
        int4 e23 = *reinterpret_cast<const int4*>(ep + k + 2);
        uint2 u0 = *reinterpret_cast<const uint2*>(srcb + (size_t)e01.x * Cc);
        uint2 u1 = *reinterpret_cast<const uint2*>(srcb + (size_t)e01.z * Cc);
        uint2 u2 = *reinterpret_cast<const uint2*>(srcb + (size_t)e23.x * Cc);
        uint2 u3 = *reinterpret_cast<const uint2*>(srcb + (size_t)e23.z * Cc);
        float v0 = __int_as_float(e01.y), v1 = __int_as_float(e01.w);
        float v2 = __int_as_float(e23.y), v3 = __int_as_float(e23.w);
        float2 a0 = h2f2(u0.x), b0 = h2f2(u0.y);
        float2 a1 = h2f2(u1.x), b1 = h2f2(u1.y);
        float2 a2 = h2f2(u2.x), b2 = h2f2(u2.y);
        float2 a3 = h2f2(u3.x), b3 = h2f2(u3.y);
        acc.x += v0 * a0.x + v1 * a1.x + v2 * a2.x + v3 * a3.x;
        acc.y += v0 * a0.y + v1 * a1.y + v2 * a2.y + v3 * a3.y;
        acc.z += v0 * b0.x + v1 * b1.x + v2 * b2.x + v3 * b3.x;
        acc.w += v0 * b0.y + v1 * b1.y + v2 * b2.y + v3 * b3.y;
    }
    for (; k < n; k++) {
        int2 cv = ep[k];
        float v = __int_as_float(cv.y);
        uint2 u = *reinterpret_cast<const uint2*>(srcb + (size_t)cv.x * Cc);
        float2 a = h2f2(u.x), b = h2f2(u.y);
        acc.x += v * a.x; acc.y += v * a.y;
        acc.z += v * b.x; acc.w += v * b.y;
    }
    uint2 o = make_uint2(f2h2(acc.x, acc.y), f2h2(acc.z, acc.w));
    *reinterpret_cast<uint2*>(dst + ((size_t)l * Gc + g) * Cc + lane * 4) = o;
}

// ---------------- kq spmm block: warp per g, 128 fp32 per row ---------------
__device__ __forceinline__ void spmmkq_block(const float* __restrict__ src,
                                             float* __restrict__ dst,
                                             int g0) {
    int w = threadIdx.x >> 5, lane = threadIdx.x & 31;
    int g = g0 + w;
    int n = g_cnt[g];
    const int2* ep = g_edgeP + (size_t)g * CAP;
    const float* srcb = src + lane * 4;
    float4 acc = make_float4(0.f, 0.f, 0.f, 0.f);
    int k = 0;
    for (; k + 4 <= n; k += 4) {
        int4 e01 = *reinterpret_cast<const int4*>(ep + k);
        int4 e23 = *reinterpret_cast<const int4*>(ep + k + 2);
        float4 s0 = *reinterpret_cast<const float4*>(srcb + (size_t)e01.x * 128);
        float4 s1 = *reinterpret_cast<const float4*>(srcb + (size_t)e01.z * 128);
        float4 s2 = *reinterpret_cast<const float4*>(srcb + (size_t)e23.x * 128);
        float4 s3 = *reinterpret_cast<const float4*>(srcb + (size_t)e23.z * 128);
        float v0 = __int_as_float(e01.y), v1 = __int_as_float(e01.w);
        float v2 = __int_as_float(e23.y), v3 = __int_as_float(e23.w);
        acc.x += v0 * s0.x + v1 * s1.x + v2 * s2.x + v3 * s3.x;
        acc.y += v0 * s0.y + v1 * s1.y + v2 * s2.y + v3 * s3.y;
        acc.z += v0 * s0.z + v1 * s1.z + v2 * s2.z + v3 * s3.z;
        acc.w += v0 * s0.w + v1 * s1.w + v2 * s2.w + v3 * s3.w;
    }
    for (; k < n; k++) {
        int2 cv = ep[k];
        float v = __int_as_float(cv.y);
        float4 sv = *reinterpret_cast<const float4*>(srcb + (size_t)cv.x * 128);
        acc.x += v * sv.x; acc.y += v * sv.y;
        acc.z += v * sv.z; acc.w += v * sv.w;
    }
    *reinterpret_cast<float4*>(dst + (size_t)g * 128 + lane * 4) = acc;
}

// ---------------- spmm1: kqx -> kqA (first), xh -> Ah -----------------------
__global__ void __launch_bounds__(256, 5)
spmm1_kernel() {
    if (blockIdx.x < KQ_BLOCKS)
        spmmkq_block(g_kqx, g_kqA, blockIdx.x * 8);
    else
        spmm16_block(g_xh, g_Ah, (blockIdx.x - KQ_BLOCKS) * 2);
}

// ---------------- spmm2: kqA -> kqB (first), Ah -> Bh -----------------------
__global__ void __launch_bounds__(256, 5)
spmm2_kernel() {
    if (blockIdx.x < KQ_BLOCKS)
        spmmkq_block(g_kqA, g_kqB, blockIdx.x * 8);
    else
        spmm16_block(g_Ah, g_Bh, (blockIdx.x - KQ_BLOCKS) * 2);
}

// ---------------- final: w from kq arrays + (x+A+B)@Wv * w + LayerNorm ------
// Block = 64 rows, 8 warps x 8 rows, lane = 4 output cols. j-paired GEMM
// with LDS.128 operand loads (ulonglong2).
__global__ void __launch_bounds__(256, 2)
final8_kernel(const float* __restrict__ x,
              const float* __restrict__ gamma,
              const float* __restrict__ beta,
              float* __restrict__ out) {
    extern __shared__ __align__(16) float dyn[];
    float* wv2 = dyn;                                    // 64KB paired Wv
    float (*s)[Cc] = reinterpret_cast<float(*)[Cc]>(dyn + Cc * Cc);  // [64][128]

    int tid = threadIdx.x;              // 256
    size_t base = (size_t)blockIdx.x * 64 * Cc;

    // stage paired Wv (64KB)
    const float4* wvg = reinterpret_cast<const float4*>(g_Wv2);
    float4* wvs = reinterpret_cast<float4*>(wv2);
    #pragma unroll
    for (int i = 0; i < 16; i++) wvs[tid + i * 256] = wvg[tid + i * 256];

    // stage s = x + A + B (A,B fp16)
    const float4* xp = reinterpret_cast<const float4*>(x + base);
    const uint2*  ap = reinterpret_cast<const uint2*>(g_Ah + base);
    const uint2*  bp = reinterpret_cast<const uint2*>(g_Bh + base);
    float4* sp = reinterpret_cast<float4*>(&s[0][0]);
    #pragma unroll
    for (int i = 0; i < 8; i++) {
        int idx = tid + i * 256;
        float4 a = xp[idx];
        uint2 ua = ap[idx], ub = bp[idx];
        float2 a0 = h2f2(ua.x), a1 = h2f2(ua.y);
        float2 b0 = h2f2(ub.x), b1 = h2f2(ub.y);
        sp[idx] = make_float4(a.x + a0.x + b0.x, a.y + a0.y + b0.y,
                              a.z + a1.x + b1.x, a.w + a1.y + b1.y);
    }

    int w = tid >> 5, lane = tid & 31;
    int row0 = w * 8;
    int Rbase = blockIdx.x * 64 + row0;

    // ---- per-row weights from fp32 kq arrays (no fp16 contamination) ----
    float wR[8];
    #pragma unroll
    for (int r = 0; r < 8; r++) {
        int R = Rbase + r;
        int l = R / Gc, g = R - l * Gc;
        float p = 0.f;
        if (lane < 16) {
            const float* kx = g_kqx + (size_t)g * 128 + l * 32;
            const float* kA = g_kqA + (size_t)g * 128 + l * 32;
            const float* kB = g_kqB + (size_t)g * 128 + l * 32;
            p = kx[lane] * kx[lane + 16] + kA[lane] * kA[lane + 16]
              + kB[lane] * kB[lane + 16];
        }
        #pragma unroll
        for (int o = 8; o; o >>= 1)
            p += __shfl_xor_sync(0xffffffffu, p, o);
        wR[r] = __shfl_sync(0xffffffffu, p, 0) * (1.0f / KDc);
    }
    __syncthreads();

    // ---- GEMM: j4-blocked, all operands via LDS.128 ----
    u64 acc[8][4];
    #pragma unroll
    for (int r = 0; r < 8; r++)
        #pragma unroll
        for (int c = 0; c < 4; c++) acc[r][c] = 0ull;

    const ulonglong2* wvu2 = reinterpret_cast<const ulonglong2*>(wv2);
    #pragma unroll 2
    for (int j4 = 0; j4 < Cc / 4; j4++) {
        // w operands for j2 = 2*j4 (a) and 2*j4+1 (b): 4 x LDS.128
        const ulonglong2* wpa = wvu2 + ((2 * j4) * Cc) / 2 + lane * 2;
        const ulonglong2* wpb = wvu2 + ((2 * j4 + 1) * Cc) / 2 + lane * 2;
        ulonglong2 wa0 = wpa[0], wa1 = wpa[1];
        ulonglong2 wb0 = wpb[0], wb1 = wpb[1];
        #pragma unroll
        for (int r = 0; r < 8; r++) {
            ulonglong2 sv = *reinterpret_cast<const ulonglong2*>(
                &s[row0 + r][j4 * 4]);                 // 1 LDS.128 broadcast
            fma2(acc[r][0], sv.x, wa0.x);
            fma2(acc[r][1], sv.x, wa0.y);
            fma2(acc[r][2], sv.x, wa1.x);
            fma2(acc[r][3], sv.x, wa1.y);
            fma2(acc[r][0], sv.y, wb0.x);
            fma2(acc[r][1], sv.y, wb0.y);
            fma2(acc[r][2], sv.y, wb1.x);
            fma2(acc[r][3], sv.y, wb1.y);
        }
    }

    // ---- scale + LayerNorm + write ----
    float4 g4 = reinterpret_cast<const float4*>(gamma)[lane];
    float4 b4 = reinterpret_cast<const float4*>(beta)[lane];

    #pragma unroll
    for (int r = 0; r < 8; r++) {
        float wt = wR[r];
        float v0 = psum(acc[r][0]) * wt;
        float v1 = psum(acc[r][1]) * wt;
        float v2 = psum(acc[r][2]) * wt;
        float v3 = psum(acc[r][3]) * wt;

        float t = v0 + v1 + v2 + v3;
        #pragma unroll
        for (int o = 16; o; o >>= 1) t += __shfl_xor_sync(0xffffffffu, t, o);
        float mu = t * (1.0f / Cc);
        float d0 = v0 - mu, d1 = v1 - mu, d2 = v2 - mu, d3 = v3 - mu;
        t = d0 * d0 + d1 * d1 + d2 * d2 + d3 * d3;
        #pragma unroll
        for (int o = 16; o; o >>= 1) t += __shfl_xor_sync(0xffffffffu, t, o);
        float rstd = rsqrtf(t * (1.0f / Cc) + LN_EPS);

        float4 o4 = make_float4(d0 * rstd * g4.x + b4.x,
                                d1 * rstd * g4.y + b4.y,
                                d2 * rstd * g4.z + b4.z,
                                d3 * rstd * g4.w + b4.w);
        reinterpret_cast<float4*>(out)[(size_t)(Rbase + r) * 32 + lane] = o4;
    }
}

// ---------------- launch ----------------------------------------------------
extern "C" void kernel_launch(void* const* d_in, const int* in_sizes, int n_in,
                              void* d_out, int out_size) {
    const float* x     = (const float*)d_in[0];
    const int*   erow  = (const int*)  d_in[1];
    const int*   ecol  = (const int*)  d_in[2];
    const float* evals = (const float*)d_in[3];
    const float* Wk    = (const float*)d_in[4];
    const float* Wq    = (const float*)d_in[5];
    const float* Wv    = (const float*)d_in[6];
    const float* gamma = (const float*)d_in[7];
    const float* beta  = (const float*)d_in[8];
    float* out = (float*)d_out;
    int E = in_sizes[1];
    if (E > Ec) E = Ec;

    setup_kernel<<<(Gc + 255) / 256, 256>>>(Wk, Wq, Wv);

    int eblk = ((E + 3) / 4 + 255) / 256;                      // 313
    scatter_prep_kernel<<<eblk + PREP_BLOCKS, 256>>>(erow, ecol, evals, E, eblk, x);

    spmm1_kernel<<<SPMM_BLOCKS + KQ_BLOCKS, 256>>>();
    spmm2_kernel<<<SPMM_BLOCKS + KQ_BLOCKS, 256>>>();

    static const int FINAL_SMEM = (Cc * Cc + 64 * Cc) * sizeof(float); // 96KB
    cudaFuncSetAttribute(final8_kernel,
                         cudaFuncAttributeMaxDynamicSharedMemorySize, FINAL_SMEM);
    final8_kernel<<<NROWS / 64, 256, FINAL_SMEM>>>(x, gamma, beta, out);
}

// round 14
// speedup vs baseline: 1.0518x; 1.0518x over previous
#include <cuda_runtime.h>
#include <cuda_fp16.h>
#include <cstdint>

// Problem constants (match reference)
#define Lc 4
#define Gc 20000
#define Cc 128
#define Ec 320000
#define KDc 16
#define NROWS (Lc*Gc)          // 80000 state rows of length 128
#define LN_EPS 1e-5f
#define CAP 192                // padded edge-bucket capacity per row

typedef unsigned long long u64;

#define PREP_BLOCKS (NROWS/32)   // 2500
#define SPMM_BLOCKS (Gc/2)       // 10000
#define KQ_BLOCKS   (Gc/8)       // 2500
#define FINAL_TILES (NROWS/64)   // 1250
#define FINAL_GRID  296          // persistent: 2 blocks x 148 SMs

// ---------------- device scratch (static: no allocation APIs) --------------
__device__ __half g_xh[(size_t)Lc*Gc*Cc];    // fp16 copy of x
__device__ __half g_Ah[(size_t)Lc*Gc*Cc];    // fp16 A = spmm(x)
__device__ __half g_Bh[(size_t)Lc*Gc*Cc];    // fp16 B = spmm(A)
__device__ float g_kqx[(size_t)Gc*128];      // [g][l*32+d] fp32 projections of x
__device__ float g_kqA[(size_t)Gc*128];      // spmm(kqx)
__device__ float g_kqB[(size_t)Gc*128];      // spmm(kqA)
__device__ int   g_cnt[Gc];                  // row degree (built by scatter)
__device__ int2  g_edgeP[(size_t)Gc*CAP];    // (col, f32bits(val*0.5)) padded
// paired layout: g_Wkq2[(j2*32+d)*2 + {0,1}] = W(2*j2, d), W(2*j2+1, d)
__device__ float g_Wkq2[(Cc/2)*32*2];
// j-paired Wv: g_Wv2[(j2*Cc + c)*2 + {0,1}] = Wv[2*j2][c], Wv[2*j2+1][c]
__device__ float g_Wv2[Cc*Cc];

// ---------------- helpers ---------------------------------------------------
__device__ __forceinline__ void fma2(u64& acc, u64 a, u64 b) {
    asm("fma.rn.f32x2 %0, %1, %2, %3;" : "=l"(acc) : "l"(a), "l"(b), "l"(acc));
}
__device__ __forceinline__ void unpack2(u64 v, float& lo, float& hi) {
    asm("mov.b64 {%0,%1}, %2;" : "=f"(lo), "=f"(hi) : "l"(v));
}
__device__ __forceinline__ float psum(u64 v) {
    float lo, hi;
    unpack2(v, lo, hi);
    return lo + hi;
}
__device__ __forceinline__ float2 h2f2(unsigned u) {
    __half2 h = *reinterpret_cast<__half2*>(&u);
    return __half22float2(h);
}
__device__ __forceinline__ unsigned f2h2(float a, float b) {
    __half2 h = __floats2half2_rn(a, b);
    return *reinterpret_cast<unsigned*>(&h);
}

// ---------------- setup: zero counters + paired Wkq2 + paired Wv2 ----------
__global__ void setup_kernel(const float* __restrict__ Wk,
                             const float* __restrict__ Wq,
                             const float* __restrict__ Wv) {
    int i = blockIdx.x * blockDim.x + threadIdx.x;
    if (i < Gc) g_cnt[i] = 0;
    if (i < (Cc / 2) * 32) {
        int j2 = i >> 5, d = i & 31;
        const float* W = (d < 16) ? Wk : Wq;
        int dd = d & 15;
        g_Wkq2[i * 2 + 0] = W[(2 * j2 + 0) * KDc + dd];
        g_Wkq2[i * 2 + 1] = W[(2 * j2 + 1) * KDc + dd];
    }
    if (i < Cc * Cc) {
        int j = i >> 7, c = i & 127;
        g_Wv2[((j >> 1) * Cc + c) * 2 + (j & 1)] = Wv[i];
    }
}

// ---------------- prep tile: kqx projections + fp16 convert of x ------------
// Block = 32 flat rows (same l; Gc%32==0). 8 warps x 4 rows; lane = kq dim.
__device__ __forceinline__ void prep_tile(const float* __restrict__ x, int b) {
    __shared__ __align__(16) float s[32][Cc];
    __shared__ __align__(16) float wkq2[(Cc/2)*32*2];
    int tid = threadIdx.x;                    // 256

    const float4* gp = reinterpret_cast<const float4*>(x + (size_t)b * 32 * Cc);
    float4* sp = reinterpret_cast<float4*>(&s[0][0]);
    const float4* wg = reinterpret_cast<const float4*>(g_Wkq2);
    float4* wsp = reinterpret_cast<float4*>(wkq2);
    #pragma unroll
    for (int i = 0; i < 4; i++) {
        sp[tid + i * 256]  = gp[tid + i * 256];
        wsp[tid + i * 256] = wg[tid + i * 256];
    }
    __syncthreads();

    // fp16 conversion of the tile (coalesced half2 writes)
    {
        const float* sf = &s[0][0];
        unsigned* dsth = reinterpret_cast<unsigned*>(g_xh + (size_t)b * 32 * Cc);
        #pragma unroll
        for (int i = 0; i < 8; i++) {
            int h = tid + i * 256;            // 2048 half2
            dsth[h] = f2h2(sf[h * 2], sf[h * 2 + 1]);
        }
    }

    int w = tid >> 5, lane = tid & 31;
    u64 acc[4] = {0ull, 0ull, 0ull, 0ull};
    #pragma unroll 8
    for (int j2 = 0; j2 < Cc / 2; j2++) {
        u64 w2 = *reinterpret_cast<const u64*>(wkq2 + (j2 * 32 + lane) * 2);
        #pragma unroll
        for (int r = 0; r < 4; r++) {
            u64 sv = *reinterpret_cast<const u64*>(&s[w * 4 + r][j2 * 2]);
            fma2(acc[r], sv, w2);
        }
    }
    int Rt = b * 32 + w * 4;
    int l = Rt / Gc, g = Rt - l * Gc;         // whole tile same l
    #pragma unroll
    for (int r = 0; r < 4; r++)
        g_kqx[(size_t)(g + r) * 128 + l * 32 + lane] = psum(acc[r]);
}

// ---------------- scatter (padded buckets) + prep ---------------------------
__global__ void scatter_prep_kernel(const int* __restrict__ erow,
                                    const int* __restrict__ ecol,
                                    const float* __restrict__ ev,
                                    int E, int eblk,
                                    const float* __restrict__ x) {
    if ((int)blockIdx.x < eblk) {
        int i = (blockIdx.x * blockDim.x + threadIdx.x) * 4;
        if (i + 3 < E) {
            int4   r = *reinterpret_cast<const int4*>(erow + i);
            int4   c = *reinterpret_cast<const int4*>(ecol + i);
            float4 v = *reinterpret_cast<const float4*>(ev + i);
            int p;
            p = atomicAdd(&g_cnt[r.x], 1);
            g_edgeP[(size_t)r.x * CAP + p] = make_int2(c.x, __float_as_int(v.x * 0.5f));
            p = atomicAdd(&g_cnt[r.y], 1);
            g_edgeP[(size_t)r.y * CAP + p] = make_int2(c.y, __float_as_int(v.y * 0.5f));
            p = atomicAdd(&g_cnt[r.z], 1);
            g_edgeP[(size_t)r.z * CAP + p] = make_int2(c.z, __float_as_int(v.z * 0.5f));
            p = atomicAdd(&g_cnt[r.w], 1);
            g_edgeP[(size_t)r.w * CAP + p] = make_int2(c.w, __float_as_int(v.w * 0.5f));
        } else {
            for (int k = i; k < E; k++) {
                int p = atomicAdd(&g_cnt[erow[k]], 1);
                g_edgeP[(size_t)erow[k] * CAP + p] =
                    make_int2(ecol[k], __float_as_int(ev[k] * 0.5f));
            }
        }
    } else {
        prep_tile(x, blockIdx.x - eblk);
    }
}

// ---------------- fp16 spmm block: 2 g x 4 l warps, LDG.64 gathers ----------
__device__ __forceinline__ void spmm16_block(const __half* __restrict__ src,
                                             __half* __restrict__ dst,
                                             int g0) {
    __shared__ __align__(16) int2 se[2][CAP];
    __shared__ int ncnt[2];
    int tid = threadIdx.x;

    if (tid < 2) ncnt[tid] = g_cnt[g0 + tid];
    __syncthreads();
    int n0 = ncnt[0], n1 = ncnt[1];
    if (tid < n0) se[0][tid] = g_edgeP[(size_t)g0 * CAP + tid];
    if (tid < n1) se[1][tid] = g_edgeP[(size_t)(g0 + 1) * CAP + tid];
    __syncthreads();

    int w = tid >> 5, lane = tid & 31;
    int gi = w >> 2;
    int g  = g0 + gi;
    int l  = w & 3;
    int n  = gi ? n1 : n0;
    const int2* ep = se[gi];
    const __half* srcb = src + (size_t)l * Gc * Cc + lane * 4;

    float4 acc = make_float4(0.f, 0.f, 0.f, 0.f);
    int k = 0;
    for (; k + 4 <= n; k += 4) {
        int4 e01 = *reinterpret_cast<const int4*>(ep + k);       // LDS broadcast
        int4 e23 = *reinterpret_cast<const int4*>(ep + k + 2);
        uint2 u0 = *reinterpret_cast<const uint2*>(srcb + (size_t)e01.x * Cc);
        uint2 u1 = *reinterpret_cast<const uint2*>(srcb + (size_t)e01.z * Cc);
        uint2 u2 = *reinterpret_cast<const uint2*>(srcb + (size_t)e23.x * Cc);
        uint2 u3 = *reinterpret_cast<const uint2*>(srcb + (size_t)e23.z * Cc);
        float v0 = __int_as_float(e01.y), v1 = __int_as_float(e01.w);
        float v2 = __int_as_float(e23.y), v3 = __int_as_float(e23.w);
        float2 a0 = h2f2(u0.x), b0 = h2f2(u0.y);
        float2 a1 = h2f2(u1.x), b1 = h2f2(u1.y);
        float2 a2 = h2f2(u2.x), b2 = h2f2(u2.y);
        float2 a3 = h2f2(u3.x), b3 = h2f2(u3.y);
        acc.x += v0 * a0.x + v1 * a1.x + v2 * a2.x + v3 * a3.x;
        acc.y += v0 * a0.y + v1 * a1.y + v2 * a2.y + v3 * a3.y;
        acc.z += v0 * b0.x + v1 * b1.x + v2 * b2.x + v3 * b3.x;
        acc.w += v0 * b0.y + v1 * b1.y + v2 * b2.y + v3 * b3.y;
    }
    for (; k < n; k++) {
        int2 cv = ep[k];
        float v = __int_as_float(cv.y);
        uint2 u = *reinterpret_cast<const uint2*>(srcb + (size_t)cv.x * Cc);
        float2 a = h2f2(u.x), b = h2f2(u.y);
        acc.x += v * a.x; acc.y += v * a.y;
        acc.z += v * b.x; acc.w += v * b.y;
    }
    uint2 o = make_uint2(f2h2(acc.x, acc.y), f2h2(acc.z, acc.w));
    *reinterpret_cast<uint2*>(dst + ((size_t)l * Gc + g) * Cc + lane * 4) = o;
}

// ---------------- kq spmm block: warp per g, 128 fp32 per row ---------------
__device__ __forceinline__ void spmmkq_block(const float* __restrict__ src,
                                             float* __restrict__ dst,
                                             int g0) {
    int w = threadIdx.x >> 5, lane = threadIdx.x & 31;
    int g = g0 + w;
    int n = g_cnt[g];
    const int2* ep = g_edgeP + (size_t)g * CAP;
    const float* srcb = src + lane * 4;
    float4 acc = make_float4(0.f, 0.f, 0.f, 0.f);
    int k = 0;
    for (; k + 4 <= n; k += 4) {
        int4 e01 = *reinterpret_cast<const int4*>(ep + k);
        int4 e23 = *reinterpret_cast<const int4*>(ep + k + 2);
        float4 s0 = *reinterpret_cast<const float4*>(srcb + (size_t)e01.x * 128);
        float4 s1 = *reinterpret_cast<const float4*>(srcb + (size_t)e01.z * 128);
        float4 s2 = *reinterpret_cast<const float4*>(srcb + (size_t)e23.x * 128);
        float4 s3 = *reinterpret_cast<const float4*>(srcb + (size_t)e23.z * 128);
        float v0 = __int_as_float(e01.y), v1 = __int_as_float(e01.w);
        float v2 = __int_as_float(e23.y), v3 = __int_as_float(e23.w);
        acc.x += v0 * s0.x + v1 * s1.x + v2 * s2.x + v3 * s3.x;
        acc.y += v0 * s0.y + v1 * s1.y + v2 * s2.y + v3 * s3.y;
        acc.z += v0 * s0.z + v1 * s1.z + v2 * s2.z + v3 * s3.z;
        acc.w += v0 * s0.w + v1 * s1.w + v2 * s2.w + v3 * s3.w;
    }
    for (; k < n; k++) {
        int2 cv = ep[k];
        float v = __int_as_float(cv.y);
        float4 sv = *reinterpret_cast<const float4*>(srcb + (size_t)cv.x * 128);
        acc.x += v * sv.x; acc.y += v * sv.y;
        acc.z += v * sv.z; acc.w += v * sv.w;
    }
    *reinterpret_cast<float4*>(dst + (size_t)g * 128 + lane * 4) = acc;
}

// ---------------- spmm1: kqx -> kqA (first), xh -> Ah -----------------------
__global__ void __launch_bounds__(256, 5)
spmm1_kernel() {
    if (blockIdx.x < KQ_BLOCKS)
        spmmkq_block(g_kqx, g_kqA, blockIdx.x * 8);
    else
        spmm16_block(g_xh, g_Ah, (blockIdx.x - KQ_BLOCKS) * 2);
}

// ---------------- spmm2: kqA -> kqB (first), Ah -> Bh -----------------------
__global__ void __launch_bounds__(256, 5)
spmm2_kernel() {
    if (blockIdx.x < KQ_BLOCKS)
        spmmkq_block(g_kqA, g_kqB, blockIdx.x * 8);
    else
        spmm16_block(g_Ah, g_Bh, (blockIdx.x - KQ_BLOCKS) * 2);
}

// ---------------- final (persistent): Wv staged once per block --------------
// Grid = 296 blocks (2/SM); each loops over tiles of 64 rows.
// GEMM: j2-paired u64 operands (final7 form — the proven fast loop).
__global__ void __launch_bounds__(256, 2)
final9_kernel(const float* __restrict__ x,
              const float* __restrict__ gamma,
              const float* __restrict__ beta,
              float* __restrict__ out) {
    extern __shared__ __align__(16) float dyn[];
    float* wv2 = dyn;                                    // 64KB paired Wv
    float (*s)[Cc] = reinterpret_cast<float(*)[Cc]>(dyn + Cc * Cc);  // [64][128]

    int tid = threadIdx.x;              // 256
    int w = tid >> 5, lane = tid & 31;
    int row0 = w * 8;

    // stage paired Wv (64KB) ONCE
    const float4* wvg = reinterpret_cast<const float4*>(g_Wv2);
    float4* wvs = reinterpret_cast<float4*>(wv2);
    #pragma unroll
    for (int i = 0; i < 16; i++) wvs[tid + i * 256] = wvg[tid + i * 256];

    float4 g4 = reinterpret_cast<const float4*>(gamma)[lane];
    float4 b4 = reinterpret_cast<const float4*>(beta)[lane];

    for (int tile = blockIdx.x; tile < FINAL_TILES; tile += FINAL_GRID) {
        size_t base = (size_t)tile * 64 * Cc;
        __syncthreads();                // s free from previous iteration

        // stage s = x + A + B (A,B fp16)
        const float4* xp = reinterpret_cast<const float4*>(x + base);
        const uint2*  ap = reinterpret_cast<const uint2*>(g_Ah + base);
        const uint2*  bp = reinterpret_cast<const uint2*>(g_Bh + base);
        float4* sp = reinterpret_cast<float4*>(&s[0][0]);
        #pragma unroll
        for (int i = 0; i < 8; i++) {
            int idx = tid + i * 256;
            float4 a = xp[idx];
            uint2 ua = ap[idx], ub = bp[idx];
            float2 a0 = h2f2(ua.x), a1 = h2f2(ua.y);
            float2 b0 = h2f2(ub.x), b1 = h2f2(ub.y);
            sp[idx] = make_float4(a.x + a0.x + b0.x, a.y + a0.y + b0.y,
                                  a.z + a1.x + b1.x, a.w + a1.y + b1.y);
        }

        int Rbase = tile * 64 + row0;

        // per-row weights from fp32 kq arrays
        float wR[8];
        #pragma unroll
        for (int r = 0; r < 8; r++) {
            int R = Rbase + r;
            int l = R / Gc, g = R - l * Gc;
            float p = 0.f;
            if (lane < 16) {
                const float* kx = g_kqx + (size_t)g * 128 + l * 32;
                const float* kA = g_kqA + (size_t)g * 128 + l * 32;
                const float* kB = g_kqB + (size_t)g * 128 + l * 32;
                p = kx[lane] * kx[lane + 16] + kA[lane] * kA[lane + 16]
                  + kB[lane] * kB[lane + 16];
            }
            #pragma unroll
            for (int o = 8; o; o >>= 1)
                p += __shfl_xor_sync(0xffffffffu, p, o);
            wR[r] = __shfl_sync(0xffffffffu, p, 0) * (1.0f / KDc);
        }
        __syncthreads();

        // GEMM: j2-paired, u64 operands
        u64 acc[8][4];
        #pragma unroll
        for (int r = 0; r < 8; r++)
            #pragma unroll
            for (int c = 0; c < 4; c++) acc[r][c] = 0ull;

        #pragma unroll 2
        for (int j2 = 0; j2 < Cc / 2; j2++) {
            const u64* wp = reinterpret_cast<const u64*>(wv2) + j2 * Cc + lane * 4;
            u64 w0 = wp[0], w1 = wp[1], w2 = wp[2], w3 = wp[3];
            #pragma unroll
            for (int r = 0; r < 8; r++) {
                u64 sv = *reinterpret_cast<const u64*>(&s[row0 + r][j2 * 2]);
                fma2(acc[r][0], sv, w0);
                fma2(acc[r][1], sv, w1);
                fma2(acc[r][2], sv, w2);
                fma2(acc[r][3], sv, w3);
            }
        }

        // scale + LayerNorm + write
        #pragma unroll
        for (int r = 0; r < 8; r++) {
            float wt = wR[r];
            float v0 = psum(acc[r][0]) * wt;
            float v1 = psum(acc[r][1]) * wt;
            float v2 = psum(acc[r][2]) * wt;
            float v3 = psum(acc[r][3]) * wt;

            float t = v0 + v1 + v2 + v3;
            #pragma unroll
            for (int o = 16; o; o >>= 1) t += __shfl_xor_sync(0xffffffffu, t, o);
            float mu = t * (1.0f / Cc);
            float d0 = v0 - mu, d1 = v1 - mu, d2 = v2 - mu, d3 = v3 - mu;
            t = d0 * d0 + d1 * d1 + d2 * d2 + d3 * d3;
            #pragma unroll
            for (int o = 16; o; o >>= 1) t += __shfl_xor_sync(0xffffffffu, t, o);
            float rstd = rsqrtf(t * (1.0f / Cc) + LN_EPS);

            float4 o4 = make_float4(d0 * rstd * g4.x + b4.x,
                                    d1 * rstd * g4.y + b4.y,
                                    d2 * rstd * g4.z + b4.z,
                                    d3 * rstd * g4.w + b4.w);
            reinterpret_cast<float4*>(out)[(size_t)(Rbase + r) * 32 + lane] = o4;
        }
    }
}

// ---------------- launch ----------------------------------------------------
extern "C" void kernel_launch(void* const* d_in, const int* in_sizes, int n_in,
                              void* d_out, int out_size) {
    const float* x     = (const float*)d_in[0];
    const int*   erow  = (const int*)  d_in[1];
    const int*   ecol  = (const int*)  d_in[2];
    const float* evals = (const float*)d_in[3];
    const float* Wk    = (const float*)d_in[4];
    const float* Wq    = (const float*)d_in[5];
    const float* Wv    = (const float*)d_in[6];
    const float* gamma = (const float*)d_in[7];
    const float* beta  = (const float*)d_in[8];
    float* out = (float*)d_out;
    int E = in_sizes[1];
    if (E > Ec) E = Ec;

    setup_kernel<<<(Gc + 255) / 256, 256>>>(Wk, Wq, Wv);

    int eblk = ((E + 3) / 4 + 255) / 256;                      // 313
    scatter_prep_kernel<<<eblk + PREP_BLOCKS, 256>>>(erow, ecol, evals, E, eblk, x);

    spmm1_kernel<<<SPMM_BLOCKS + KQ_BLOCKS, 256>>>();
    spmm2_kernel<<<SPMM_BLOCKS + KQ_BLOCKS, 256>>>();

    static const int FINAL_SMEM = (Cc * Cc + 64 * Cc) * sizeof(float); // 96KB
    cudaFuncSetAttribute(final9_kernel,
                         cudaFuncAttributeMaxDynamicSharedMemorySize, FINAL_SMEM);
    final9_kernel<<<FINAL_GRID, 256, FINAL_SMEM>>>(x, gamma, beta, out);
}